// round 15
// baseline (speedup 1.0000x reference)
#include <cuda_runtime.h>

#define RES 512
#define BATCH 128
#define NC 10
#define CH 32                      // images per L2-resident chunk (67 MB < 126 MB L2)
#define BUFSZ 574                  // even (16B-aligned buffers); >= max(P1(511)=573, P2(511)=567)
// Per-exchange conflict-free paddings (verified per half-warp / quarter-warp):
#define P1(i) ((i) + 2 * ((i) >> 4))   // exchange 1: STS.128 stores + LDS.64 loads conflict-free
#define P2(i) ((i) + 8 * ((i) >> 6))   // exchange 2 + k_col staging: both sides conflict-free

// ---- device-global scratch (allocation-free rule) ----
__device__ float2 g_field[(size_t)BATCH * RES * RES];
__device__ float  g_partial[(size_t)BATCH * RES * NC];
__device__ float2 g_phexp[(size_t)3 * RES * RES];  // exp(i*phase), layer-major
__device__ float2 g_gx[RES];    // exp(-i*pi*lam*z*fx^2)
__device__ float2 g_gcol[RES];  // exp(i*K*Z)*exp(-i*pi*lam*z*fy^2) / (RES*RES)

__device__ __forceinline__ float2 cmul(float2 a, float2 b) {
    return make_float2(fmaf(a.x, b.x, -a.y * b.y), fmaf(a.x, b.y, a.y * b.x));
}
__device__ __forceinline__ float2 cadd(float2 a, float2 b) { return make_float2(a.x + b.x, a.y + b.y); }
__device__ __forceinline__ float2 csub(float2 a, float2 b) { return make_float2(a.x - b.x, a.y - b.y); }
__device__ __forceinline__ float2 cconj(float2 a) { return make_float2(a.x, -a.y); }
__device__ __forceinline__ float2 mul_mi(float2 a) { return make_float2(a.y, -a.x); }  // * -i
__device__ __forceinline__ float2 mul_pi(float2 a) { return make_float2(-a.y, a.x); }  // * +i

__device__ __forceinline__ void gbar(int id) {
    asm volatile("bar.sync %0, 64;" :: "r"(id) : "memory");
}

// Natural-order DFT-8, W = exp(-2*pi*i/8)
__device__ __forceinline__ void dft8(float2 v[8]) {
    const float S = 0.70710678118654752440f;
    float2 a00 = cadd(v[0], v[4]), a01 = csub(v[0], v[4]);
    float2 a10 = cadd(v[1], v[5]), a11 = csub(v[1], v[5]);
    float2 a20 = cadd(v[2], v[6]), a21 = csub(v[2], v[6]);
    float2 a30 = cadd(v[3], v[7]), a31 = csub(v[3], v[7]);
    float2 b00 = cadd(a00, a20), b02 = csub(a00, a20);
    float2 b01 = cadd(a01, mul_mi(a21)), b03 = cadd(a01, mul_pi(a21));
    float2 b10 = cadd(a10, a30), b12 = csub(a10, a30);
    float2 b11 = cadd(a11, mul_mi(a31)), b13 = cadd(a11, mul_pi(a31));
    float2 w1b11 = make_float2(S * (b11.x + b11.y), S * (b11.y - b11.x));   // W^1 * b11
    float2 w3b13 = make_float2(S * (b13.y - b13.x), -S * (b13.x + b13.y));  // W^3 * b13
    v[0] = cadd(b00, b10);          v[4] = csub(b00, b10);
    v[1] = cadd(b01, w1b11);        v[5] = csub(b01, w1b11);
    v[2] = cadd(b02, mul_mi(b12));  v[6] = cadd(b02, mul_pi(b12));
    v[3] = cadd(b03, w3b13);        v[7] = csub(b03, w3b13);
}

// Log-depth twiddle powers: w^1..w^7 with product depth 3.
#define TW_POWERS(ANG)                                   \
    float s_, c_; __sincosf((ANG), &s_, &c_);            \
    float2 w1 = make_float2(c_, s_);                     \
    float2 w2 = cmul(w1, w1);                            \
    float2 w3 = cmul(w2, w1);                            \
    float2 w4 = cmul(w2, w2);                            \
    float2 w5 = cmul(w3, w2);                            \
    float2 w6 = cmul(w3, w3);                            \
    float2 w7 = cmul(w4, w3);

// Vectorized exchange-1 store: run P1(8j+r) = 8j+2(j>>1)+r is 8 contiguous
// float2 (16B aligned: index even, buffers 16B aligned).
__device__ __forceinline__ void st1_vec(float2* A, int j, const float2 v[8]) {
    float4* A4 = reinterpret_cast<float4*>(A + (8 * j + 2 * (j >> 1)));
#pragma unroll
    for (int q = 0; q < 4; q++)
        A4[q] = make_float4(v[2 * q].x, v[2 * q].y, v[2 * q + 1].x, v[2 * q + 1].y);
}

// ---- DUAL register-resident Stockham radix-8 512-pt FFT ----
// Two independent FFTs (va in buffer A, vb in buffer B) share barriers and
// twiddle sincos. v[r] holds element (j + 64*r), natural order, 64 thr/group.
// Barriers: [B1: WAR vs prior readers] store1 / RAW / WAR(b3: exchange-1 loads
// before exchange-2 stores — REQUIRED, P1/P2 slots overlap) store2 / RAW.
template <bool B1>
__device__ __forceinline__ void fft512_reg2(float2 va[8], float2 vb[8], int j,
                                            float2* A, float2* B, int barid) {
    dft8(va); dft8(vb);
    if (B1) gbar(barid);          // WAR: prior readers of the smem region done
    st1_vec(A, j, va); st1_vec(B, j, vb);
    gbar(barid);                  // RAW
    {
        const int lb = j + 2 * (j >> 4);   // P1(j+64r) = lb + 72r
#pragma unroll
        for (int r = 0; r < 8; r++) { va[r] = A[lb + 72 * r]; vb[r] = B[lb + 72 * r]; }
    }
    {   // shared stage-1 twiddle: exp(-2*pi*i*(j&7)/64)
        TW_POWERS(-6.2831853071795864769f * (float)(j & 7) * (1.0f / 64.0f));
        va[1] = cmul(va[1], w1); vb[1] = cmul(vb[1], w1);
        va[2] = cmul(va[2], w2); vb[2] = cmul(vb[2], w2);
        va[3] = cmul(va[3], w3); vb[3] = cmul(vb[3], w3);
        va[4] = cmul(va[4], w4); vb[4] = cmul(vb[4], w4);
        va[5] = cmul(va[5], w5); vb[5] = cmul(vb[5], w5);
        va[6] = cmul(va[6], w6); vb[6] = cmul(vb[6], w6);
        va[7] = cmul(va[7], w7); vb[7] = cmul(vb[7], w7);
    }
    dft8(va); dft8(vb);
    gbar(barid);                  // WAR (b3): all exchange-1 loads done before overwrite
    {   // exchange-2 store: P2(d) = 72*(j>>3) + (j&7) + 8r
        const int sb = 72 * (j >> 3) + (j & 7);
#pragma unroll
        for (int r = 0; r < 8; r++) { A[sb + 8 * r] = va[r]; B[sb + 8 * r] = vb[r]; }
    }
    gbar(barid);                  // RAW
#pragma unroll
    for (int r = 0; r < 8; r++) { va[r] = A[j + 72 * r]; vb[r] = B[j + 72 * r]; }  // P2(j+64r)=j+72r
    {   // shared stage-2 twiddle: exp(-2*pi*i*j/512)
        TW_POWERS(-6.2831853071795864769f * (float)j * (1.0f / 512.0f));
        va[1] = cmul(va[1], w1); vb[1] = cmul(vb[1], w1);
        va[2] = cmul(va[2], w2); vb[2] = cmul(vb[2], w2);
        va[3] = cmul(va[3], w3); vb[3] = cmul(vb[3], w3);
        va[4] = cmul(va[4], w4); vb[4] = cmul(vb[4], w4);
        va[5] = cmul(va[5], w5); vb[5] = cmul(vb[5], w5);
        va[6] = cmul(va[6], w6); vb[6] = cmul(vb[6], w6);
        va[7] = cmul(va[7], w7); vb[7] = cmul(vb[7], w7);
    }
    dft8(va); dft8(vb);
    // v[r] = X[j + 64*r]
}

// Single-stream variant (final pass: FC accumulators eat registers)
template <bool B1>
__device__ __forceinline__ void fft512_reg(float2 v[8], int j, float2* A, int barid) {
    dft8(v);
    if (B1) gbar(barid);
    st1_vec(A, j, v);
    gbar(barid);
    {
        const int lb = j + 2 * (j >> 4);
#pragma unroll
        for (int r = 0; r < 8; r++) v[r] = A[lb + 72 * r];
    }
    {
        TW_POWERS(-6.2831853071795864769f * (float)(j & 7) * (1.0f / 64.0f));
        v[1] = cmul(v[1], w1); v[2] = cmul(v[2], w2); v[3] = cmul(v[3], w3);
        v[4] = cmul(v[4], w4); v[5] = cmul(v[5], w5); v[6] = cmul(v[6], w6);
        v[7] = cmul(v[7], w7);
    }
    dft8(v);
    gbar(barid);                  // WAR (b3)
    {
        const int sb = 72 * (j >> 3) + (j & 7);
#pragma unroll
        for (int r = 0; r < 8; r++) A[sb + 8 * r] = v[r];
    }
    gbar(barid);
#pragma unroll
    for (int r = 0; r < 8; r++) v[r] = A[j + 72 * r];
    {
        TW_POWERS(-6.2831853071795864769f * (float)j * (1.0f / 512.0f));
        v[1] = cmul(v[1], w1); v[2] = cmul(v[2], w2); v[3] = cmul(v[3], w3);
        v[4] = cmul(v[4], w4); v[5] = cmul(v[5], w5); v[6] = cmul(v[6], w6);
        v[7] = cmul(v[7], w7);
    }
    dft8(v);
}

// ---- table init (fp64 phase to match numpy's float64 H) ----
__global__ void k_init() {
    int f = threadIdx.x;
    if (f >= RES) return;
    const double PI = 3.14159265358979323846;
    const double lam = 5.32e-07, z = 0.035, dx = 1e-06;
    double fx = ((f < RES / 2) ? (double)f : (double)(f - RES)) / ((double)RES * dx);
    double ang = -PI * lam * z * fx * fx;
    double s, c;
    sincos(ang, &s, &c);
    g_gx[f] = make_float2((float)c, (float)s);
    double kz = (2.0 * PI / lam) * z;
    double s2, c2;
    sincos(ang + kz, &s2, &c2);
    double inv = 1.0 / ((double)RES * (double)RES);
    g_gcol[f] = make_float2((float)(c2 * inv), (float)(s2 * inv));
}

// ---- phase exponential precompute: g_phexp = exp(i*phases) ----
__global__ void k_phexp(const float* __restrict__ phases) {
    size_t i = (size_t)blockIdx.x * 1024 + threadIdx.x;
    float s, c;
    __sincosf(phases[i], &s, &c);
    g_phexp[i] = make_float2(c, s);
}

// ---- layer-0 row pass (dual): x * e^{i phi0} -> FFT -> * g(fx) ----
__global__ void __launch_bounds__(128, 4)
k_row_first(const float* __restrict__ x, int row0) {
    extern __shared__ float2 sm[];
    const int g = threadIdx.x >> 6, j = threadIdx.x & 63;
    const int rowA = row0 + blockIdx.x * 4 + g * 2;
    const int yA = rowA & 511;
    const float* xrA = x + (size_t)rowA * RES;
    const float* xrB = xrA + RES;
    const float2* peA = g_phexp + (size_t)yA * RES;
    const float2* peB = peA + RES;
    float2* A = sm + (size_t)(2 * g) * BUFSZ;
    float2* B = A + BUFSZ;
    float2 va[8], vb[8];
#pragma unroll
    for (int r = 0; r < 8; r++) {
        int i = j + r * 64;
        float2 ea = peA[i], eb = peB[i];
        float xa = xrA[i], xb = xrB[i];
        va[r] = make_float2(xa * ea.x, xa * ea.y);
        vb[r] = make_float2(xb * eb.x, xb * eb.y);
    }
    fft512_reg2<false>(va, vb, j, A, B, 1 + g);   // no prior smem readers
    float2* outA = g_field + (size_t)rowA * RES;
    float2* outB = outA + RES;
#pragma unroll
    for (int r = 0; r < 8; r++) {
        int f = j + r * 64;
        float2 gx = g_gx[f];
        outA[f] = cmul(va[r], gx);
        outB[f] = cmul(vb[r], gx);
    }
}

// ---- mid row pass (dual): unnorm IFFT -> * e^{i phi} -> FFT -> * g(fx) ----
__global__ void __launch_bounds__(128, 4)
k_row_mid(int layer, int row0) {
    extern __shared__ float2 sm[];
    const int g = threadIdx.x >> 6, j = threadIdx.x & 63;
    const int rowA = row0 + blockIdx.x * 4 + g * 2;
    const int yA = rowA & 511;
    const float2* peA = g_phexp + (size_t)layer * RES * RES + (size_t)yA * RES;
    const float2* peB = peA + RES;
    float2* A = sm + (size_t)(2 * g) * BUFSZ;
    float2* B = A + BUFSZ;
    float2* inA = g_field + (size_t)rowA * RES;
    float2* inB = inA + RES;
    float2 va[8], vb[8];
#pragma unroll
    for (int r = 0; r < 8; r++) {
        int i = j + r * 64;
        va[r] = cconj(inA[i]);   // IFFT via conj-FFT-conj
        vb[r] = cconj(inB[i]);
    }
    fft512_reg2<false>(va, vb, j, A, B, 1 + g);   // first call: no prior readers
#pragma unroll
    for (int r = 0; r < 8; r++) {
        int i = j + r * 64;
        va[r] = cmul(cconj(va[r]), peA[i]);
        vb[r] = cmul(cconj(vb[r]), peB[i]);
    }
    fft512_reg2<true>(va, vb, j, A, B, 1 + g);    // WAR vs call-1's last loads
#pragma unroll
    for (int r = 0; r < 8; r++) {
        int f = j + r * 64;
        float2 gx = g_gx[f];
        inA[f] = cmul(va[r], gx);
        inB[f] = cmul(vb[r], gx);
    }
}

// ---- column pass (dual): FFT(col) -> * gcol -> unnorm IFFT(col), 8 cols/block ----
// Staging uses the P2 mapping; BUFSZ=574 -> cc bank-spacing 28, conflict-free.
__global__ void __launch_bounds__(256, 2)
k_col(int b0) {
    extern __shared__ float2 sm[];
    const int tid = threadIdx.x;
    const int g = tid >> 6, j = tid & 63;
    const int b = b0 + blockIdx.x;
    const int c0 = blockIdx.y * 8;
    float2* base = g_field + (size_t)b * RES * RES + c0;
    // cooperative transposed load: 8 consecutive threads read 8 consecutive cols (64B)
#pragma unroll
    for (int i = 0; i < 16; i++) {
        int rowi = i * 32 + (tid >> 3);
        int cc = tid & 7;
        sm[(size_t)cc * BUFSZ + P2(rowi)] = base[(size_t)rowi * RES + cc];
    }
    __syncthreads();
    float2* A = sm + (size_t)(2 * g) * BUFSZ;
    float2* B = A + BUFSZ;
    float2 va[8], vb[8];
#pragma unroll
    for (int r = 0; r < 8; r++) { va[r] = A[j + 72 * r]; vb[r] = B[j + 72 * r]; }  // P2(j+64r)
    fft512_reg2<true>(va, vb, j, A, B, 1 + g);    // WAR vs other threads' staged loads
#pragma unroll
    for (int r = 0; r < 8; r++) {
        int f = j + r * 64;
        float2 gc = g_gcol[f];
        va[r] = cconj(cmul(va[r], gc));
        vb[r] = cconj(cmul(vb[r], gc));
    }
    fft512_reg2<true>(va, vb, j, A, B, 1 + g);
    // each thread rewrites exactly the P2 slots it read in the last stage — no hazard
#pragma unroll
    for (int r = 0; r < 8; r++) {
        A[j + 72 * r] = cconj(va[r]);
        B[j + 72 * r] = cconj(vb[r]);
    }
    __syncthreads();
#pragma unroll
    for (int i = 0; i < 16; i++) {
        int rowi = i * 32 + (tid >> 3);
        int cc = tid & 7;
        base[(size_t)rowi * RES + cc] = sm[(size_t)cc * BUFSZ + P2(rowi)];
    }
}

// ---- final row pass: unnorm IFFT(row) -> intensity -> per-row dot with fc_w ----
__global__ void __launch_bounds__(128, 4)
k_row_final(const float* __restrict__ fc_w, int row0) {
    extern __shared__ float2 sm[];
    __shared__ float smred[2][2][NC];
    const int g = threadIdx.x >> 6, j = threadIdx.x & 63;
    const int row = row0 + blockIdx.x * 2 + g;
    const int y = row & 511;
    float2* A = sm + (size_t)g * BUFSZ;
    float2* inrow = g_field + (size_t)row * RES;
    float2 v[8];
#pragma unroll
    for (int r = 0; r < 8; r++) v[r] = cconj(inrow[j + r * 64]);
    fft512_reg<false>(v, j, A, 1 + g);   // |conj(.)|^2 == |.|^2, skip final conj
    float acc[NC];
#pragma unroll
    for (int c = 0; c < NC; c++) acc[c] = 0.0f;
#pragma unroll
    for (int r = 0; r < 8; r++) {
        int i = j + r * 64;
        float2 t = v[r];
        float I = t.x * t.x + t.y * t.y;
        size_t col = (size_t)y * RES + i;
#pragma unroll
        for (int c = 0; c < NC; c++) acc[c] += I * fc_w[(size_t)c * (RES * RES) + col];
    }
#pragma unroll
    for (int c = 0; c < NC; c++) {
#pragma unroll
        for (int off = 16; off > 0; off >>= 1)
            acc[c] += __shfl_down_sync(0xffffffffu, acc[c], off);
    }
    const int lane = j & 31;
    const int half = j >> 5;
    if (lane == 0) {
#pragma unroll
        for (int c = 0; c < NC; c++) smred[g][half][c] = acc[c];
    }
    __syncthreads();
    if (j < NC) g_partial[(size_t)row * NC + j] = smred[g][0][j] + smred[g][1][j];
}

// ---- final reduce: out[b][c] = fc_b[c] + sum_y partial[b*512+y][c] ----
__global__ void k_fc_reduce(const float* __restrict__ fc_b, float* __restrict__ out) {
    const int b = blockIdx.x;
    const int w = threadIdx.x >> 5;
    const int l = threadIdx.x & 31;
    if (w >= NC) return;
    float s = 0.0f;
    for (int y = l; y < RES; y += 32)
        s += g_partial[((size_t)(b << 9) + y) * NC + w];
#pragma unroll
    for (int off = 16; off > 0; off >>= 1)
        s += __shfl_down_sync(0xffffffffu, s, off);
    if (l == 0) out[b * NC + w] = s + fc_b[w];
}

extern "C" void kernel_launch(void* const* d_in, const int* in_sizes, int n_in,
                              void* d_out, int out_size) {
    (void)in_sizes; (void)n_in; (void)out_size;
    const float* x      = (const float*)d_in[0];
    const float* phases = (const float*)d_in[1];
    const float* fc_w   = (const float*)d_in[2];
    const float* fc_b   = (const float*)d_in[3];
    float* out = (float*)d_out;

    const size_t SMEM_ROW  = (size_t)4 * BUFSZ * sizeof(float2);  // 18368 B
    const size_t SMEM_COL  = (size_t)8 * BUFSZ * sizeof(float2);  // 36736 B
    const size_t SMEM_FIN  = (size_t)2 * BUFSZ * sizeof(float2);  //  9184 B
    const int ROW_BLOCKS = CH * RES / 4;                          // 4096 per chunk
    const int FIN_BLOCKS = CH * RES / 2;                          // 8192 per chunk
    const int N_CHUNKS = BATCH / CH;                              // 4

    k_init<<<1, RES>>>();
    k_phexp<<<3 * RES * RES / 1024, 1024>>>(phases);
    // Whole 7-pass pipeline per 32-image chunk: working set stays in L2.
    for (int c = 0; c < N_CHUNKS; c++) {
        const int b0 = c * CH;
        const int row0 = b0 * RES;
        k_row_first<<<ROW_BLOCKS, 128, SMEM_ROW>>>(x, row0);
        for (int layer = 0; layer < 3; layer++) {
            k_col<<<dim3(CH, RES / 8), 256, SMEM_COL>>>(b0);
            if (layer < 2)
                k_row_mid<<<ROW_BLOCKS, 128, SMEM_ROW>>>(layer + 1, row0);
        }
        k_row_final<<<FIN_BLOCKS, 128, SMEM_FIN>>>(fc_w, row0);
    }
    k_fc_reduce<<<BATCH, 320>>>(fc_b, out);
}

// round 16
// speedup vs baseline: 1.0070x; 1.0070x over previous
#include <cuda_runtime.h>

#define RES 512
#define BATCH 128
#define NC 10
#define CH 32                      // images per L2-resident chunk (67 MB < 126 MB L2)
#define BUFSZ 574                  // even (16B-aligned buffers); >= max(P1(511)=573, P2(511)=567)
// Per-exchange conflict-free paddings (verified per half-warp / quarter-warp):
#define P1(i) ((i) + 2 * ((i) >> 4))   // exchange 1: STS.128 stores + LDS.64 loads conflict-free
#define P2(i) ((i) + 8 * ((i) >> 6))   // exchange 2 + k_col staging: both sides conflict-free

// ---- device-global scratch (allocation-free rule) ----
__device__ float2 g_field[(size_t)BATCH * RES * RES];
__device__ float  g_partial[(size_t)BATCH * RES * NC];
__device__ float2 g_phexp[(size_t)3 * RES * RES];  // exp(i*phase), layer-major
__device__ float2 g_gx[RES];    // exp(-i*pi*lam*z*fx^2)
__device__ float2 g_gcol[RES];  // exp(i*K*Z)*exp(-i*pi*lam*z*fy^2) / (RES*RES)

__device__ __forceinline__ float2 cmul(float2 a, float2 b) {
    return make_float2(fmaf(a.x, b.x, -a.y * b.y), fmaf(a.x, b.y, a.y * b.x));
}
__device__ __forceinline__ float2 cadd(float2 a, float2 b) { return make_float2(a.x + b.x, a.y + b.y); }
__device__ __forceinline__ float2 csub(float2 a, float2 b) { return make_float2(a.x - b.x, a.y - b.y); }
__device__ __forceinline__ float2 cconj(float2 a) { return make_float2(a.x, -a.y); }
__device__ __forceinline__ float2 mul_mi(float2 a) { return make_float2(a.y, -a.x); }  // * -i
__device__ __forceinline__ float2 mul_pi(float2 a) { return make_float2(-a.y, a.x); }  // * +i

__device__ __forceinline__ void gbar(int id) {
    asm volatile("bar.sync %0, 64;" :: "r"(id) : "memory");
}

// Natural-order DFT-8, W = exp(-2*pi*i/8)
__device__ __forceinline__ void dft8(float2 v[8]) {
    const float S = 0.70710678118654752440f;
    float2 a00 = cadd(v[0], v[4]), a01 = csub(v[0], v[4]);
    float2 a10 = cadd(v[1], v[5]), a11 = csub(v[1], v[5]);
    float2 a20 = cadd(v[2], v[6]), a21 = csub(v[2], v[6]);
    float2 a30 = cadd(v[3], v[7]), a31 = csub(v[3], v[7]);
    float2 b00 = cadd(a00, a20), b02 = csub(a00, a20);
    float2 b01 = cadd(a01, mul_mi(a21)), b03 = cadd(a01, mul_pi(a21));
    float2 b10 = cadd(a10, a30), b12 = csub(a10, a30);
    float2 b11 = cadd(a11, mul_mi(a31)), b13 = cadd(a11, mul_pi(a31));
    float2 w1b11 = make_float2(S * (b11.x + b11.y), S * (b11.y - b11.x));   // W^1 * b11
    float2 w3b13 = make_float2(S * (b13.y - b13.x), -S * (b13.x + b13.y));  // W^3 * b13
    v[0] = cadd(b00, b10);          v[4] = csub(b00, b10);
    v[1] = cadd(b01, w1b11);        v[5] = csub(b01, w1b11);
    v[2] = cadd(b02, mul_mi(b12));  v[6] = cadd(b02, mul_pi(b12));
    v[3] = cadd(b03, w3b13);        v[7] = csub(b03, w3b13);
}

// Log-depth twiddle powers: w^1..w^7 with product depth 3.
#define TW_POWERS(ANG)                                   \
    float s_, c_; __sincosf((ANG), &s_, &c_);            \
    float2 w1 = make_float2(c_, s_);                     \
    float2 w2 = cmul(w1, w1);                            \
    float2 w3 = cmul(w2, w1);                            \
    float2 w4 = cmul(w2, w2);                            \
    float2 w5 = cmul(w3, w2);                            \
    float2 w6 = cmul(w3, w3);                            \
    float2 w7 = cmul(w4, w3);

// Vectorized exchange-1 store: run P1(8j+r) = 8j+2(j>>1)+r is 8 contiguous
// float2 (16B aligned: index even, buffers 16B aligned).
__device__ __forceinline__ void st1_vec(float2* A, int j, const float2 v[8]) {
    float4* A4 = reinterpret_cast<float4*>(A + (8 * j + 2 * (j >> 1)));
#pragma unroll
    for (int q = 0; q < 4; q++)
        A4[q] = make_float4(v[2 * q].x, v[2 * q].y, v[2 * q + 1].x, v[2 * q + 1].y);
}

// ---- DUAL register-resident Stockham radix-8 512-pt FFT ----
// Two independent FFTs (va in buffer A, vb in buffer B) share barriers and
// twiddle sincos. v[r] holds element (j + 64*r), natural order, 64 thr/group.
// Barriers: [B1: WAR vs prior readers] store1 / RAW / WAR(b3: exchange-1 loads
// before exchange-2 stores — REQUIRED, P1/P2 slots overlap) store2 / RAW.
template <bool B1>
__device__ __forceinline__ void fft512_reg2(float2 va[8], float2 vb[8], int j,
                                            float2* A, float2* B, int barid) {
    dft8(va); dft8(vb);
    if (B1) gbar(barid);          // WAR: prior readers of the smem region done
    st1_vec(A, j, va); st1_vec(B, j, vb);
    gbar(barid);                  // RAW
    {
        const int lb = j + 2 * (j >> 4);   // P1(j+64r) = lb + 72r
#pragma unroll
        for (int r = 0; r < 8; r++) { va[r] = A[lb + 72 * r]; vb[r] = B[lb + 72 * r]; }
    }
    {   // shared stage-1 twiddle: exp(-2*pi*i*(j&7)/64)
        TW_POWERS(-6.2831853071795864769f * (float)(j & 7) * (1.0f / 64.0f));
        va[1] = cmul(va[1], w1); vb[1] = cmul(vb[1], w1);
        va[2] = cmul(va[2], w2); vb[2] = cmul(vb[2], w2);
        va[3] = cmul(va[3], w3); vb[3] = cmul(vb[3], w3);
        va[4] = cmul(va[4], w4); vb[4] = cmul(vb[4], w4);
        va[5] = cmul(va[5], w5); vb[5] = cmul(vb[5], w5);
        va[6] = cmul(va[6], w6); vb[6] = cmul(vb[6], w6);
        va[7] = cmul(va[7], w7); vb[7] = cmul(vb[7], w7);
    }
    dft8(va); dft8(vb);
    gbar(barid);                  // WAR (b3): all exchange-1 loads done before overwrite
    {   // exchange-2 store: P2(d) = 72*(j>>3) + (j&7) + 8r
        const int sb = 72 * (j >> 3) + (j & 7);
#pragma unroll
        for (int r = 0; r < 8; r++) { A[sb + 8 * r] = va[r]; B[sb + 8 * r] = vb[r]; }
    }
    gbar(barid);                  // RAW
#pragma unroll
    for (int r = 0; r < 8; r++) { va[r] = A[j + 72 * r]; vb[r] = B[j + 72 * r]; }  // P2(j+64r)=j+72r
    {   // shared stage-2 twiddle: exp(-2*pi*i*j/512)
        TW_POWERS(-6.2831853071795864769f * (float)j * (1.0f / 512.0f));
        va[1] = cmul(va[1], w1); vb[1] = cmul(vb[1], w1);
        va[2] = cmul(va[2], w2); vb[2] = cmul(vb[2], w2);
        va[3] = cmul(va[3], w3); vb[3] = cmul(vb[3], w3);
        va[4] = cmul(va[4], w4); vb[4] = cmul(vb[4], w4);
        va[5] = cmul(va[5], w5); vb[5] = cmul(vb[5], w5);
        va[6] = cmul(va[6], w6); vb[6] = cmul(vb[6], w6);
        va[7] = cmul(va[7], w7); vb[7] = cmul(vb[7], w7);
    }
    dft8(va); dft8(vb);
    // v[r] = X[j + 64*r]
}

// Single-stream variant (final pass: FC accumulators eat registers)
template <bool B1>
__device__ __forceinline__ void fft512_reg(float2 v[8], int j, float2* A, int barid) {
    dft8(v);
    if (B1) gbar(barid);
    st1_vec(A, j, v);
    gbar(barid);
    {
        const int lb = j + 2 * (j >> 4);
#pragma unroll
        for (int r = 0; r < 8; r++) v[r] = A[lb + 72 * r];
    }
    {
        TW_POWERS(-6.2831853071795864769f * (float)(j & 7) * (1.0f / 64.0f));
        v[1] = cmul(v[1], w1); v[2] = cmul(v[2], w2); v[3] = cmul(v[3], w3);
        v[4] = cmul(v[4], w4); v[5] = cmul(v[5], w5); v[6] = cmul(v[6], w6);
        v[7] = cmul(v[7], w7);
    }
    dft8(v);
    gbar(barid);                  // WAR (b3)
    {
        const int sb = 72 * (j >> 3) + (j & 7);
#pragma unroll
        for (int r = 0; r < 8; r++) A[sb + 8 * r] = v[r];
    }
    gbar(barid);
#pragma unroll
    for (int r = 0; r < 8; r++) v[r] = A[j + 72 * r];
    {
        TW_POWERS(-6.2831853071795864769f * (float)j * (1.0f / 512.0f));
        v[1] = cmul(v[1], w1); v[2] = cmul(v[2], w2); v[3] = cmul(v[3], w3);
        v[4] = cmul(v[4], w4); v[5] = cmul(v[5], w5); v[6] = cmul(v[6], w6);
        v[7] = cmul(v[7], w7);
    }
    dft8(v);
}

// ---- table init (fp64 phase to match numpy's float64 H) ----
__global__ void k_init() {
    int f = threadIdx.x;
    if (f >= RES) return;
    const double PI = 3.14159265358979323846;
    const double lam = 5.32e-07, z = 0.035, dx = 1e-06;
    double fx = ((f < RES / 2) ? (double)f : (double)(f - RES)) / ((double)RES * dx);
    double ang = -PI * lam * z * fx * fx;
    double s, c;
    sincos(ang, &s, &c);
    g_gx[f] = make_float2((float)c, (float)s);
    double kz = (2.0 * PI / lam) * z;
    double s2, c2;
    sincos(ang + kz, &s2, &c2);
    double inv = 1.0 / ((double)RES * (double)RES);
    g_gcol[f] = make_float2((float)(c2 * inv), (float)(s2 * inv));
}

// ---- phase exponential precompute: g_phexp = exp(i*phases) ----
__global__ void k_phexp(const float* __restrict__ phases) {
    size_t i = (size_t)blockIdx.x * 1024 + threadIdx.x;
    float s, c;
    __sincosf(phases[i], &s, &c);
    g_phexp[i] = make_float2(c, s);
}

// ---- layer-0 row pass (dual): x * e^{i phi0} -> FFT -> * g(fx) ----
__global__ void __launch_bounds__(128, 4)
k_row_first(const float* __restrict__ x, int row0) {
    extern __shared__ float2 sm[];
    const int g = threadIdx.x >> 6, j = threadIdx.x & 63;
    const int rowA = row0 + blockIdx.x * 4 + g * 2;
    const int yA = rowA & 511;
    const float* xrA = x + (size_t)rowA * RES;
    const float* xrB = xrA + RES;
    const float2* peA = g_phexp + (size_t)yA * RES;
    const float2* peB = peA + RES;
    float2* A = sm + (size_t)(2 * g) * BUFSZ;
    float2* B = A + BUFSZ;
    float2 va[8], vb[8];
#pragma unroll
    for (int r = 0; r < 8; r++) {
        int i = j + r * 64;
        float2 ea = peA[i], eb = peB[i];
        float xa = xrA[i], xb = xrB[i];
        va[r] = make_float2(xa * ea.x, xa * ea.y);
        vb[r] = make_float2(xb * eb.x, xb * eb.y);
    }
    fft512_reg2<false>(va, vb, j, A, B, 1 + g);   // no prior smem readers
    float2* outA = g_field + (size_t)rowA * RES;
    float2* outB = outA + RES;
#pragma unroll
    for (int r = 0; r < 8; r++) {
        int f = j + r * 64;
        float2 gx = g_gx[f];
        outA[f] = cmul(va[r], gx);
        outB[f] = cmul(vb[r], gx);
    }
}

// ---- mid row pass (dual): unnorm IFFT -> * e^{i phi} -> FFT -> * g(fx) ----
__global__ void __launch_bounds__(128, 4)
k_row_mid(int layer, int row0) {
    extern __shared__ float2 sm[];
    const int g = threadIdx.x >> 6, j = threadIdx.x & 63;
    const int rowA = row0 + blockIdx.x * 4 + g * 2;
    const int yA = rowA & 511;
    const float2* peA = g_phexp + (size_t)layer * RES * RES + (size_t)yA * RES;
    const float2* peB = peA + RES;
    float2* A = sm + (size_t)(2 * g) * BUFSZ;
    float2* B = A + BUFSZ;
    float2* inA = g_field + (size_t)rowA * RES;
    float2* inB = inA + RES;
    float2 va[8], vb[8];
#pragma unroll
    for (int r = 0; r < 8; r++) {
        int i = j + r * 64;
        va[r] = cconj(inA[i]);   // IFFT via conj-FFT-conj
        vb[r] = cconj(inB[i]);
    }
    fft512_reg2<false>(va, vb, j, A, B, 1 + g);   // first call: no prior readers
#pragma unroll
    for (int r = 0; r < 8; r++) {
        int i = j + r * 64;
        va[r] = cmul(cconj(va[r]), peA[i]);
        vb[r] = cmul(cconj(vb[r]), peB[i]);
    }
    fft512_reg2<true>(va, vb, j, A, B, 1 + g);    // WAR vs call-1's last loads
#pragma unroll
    for (int r = 0; r < 8; r++) {
        int f = j + r * 64;
        float2 gx = g_gx[f];
        inA[f] = cmul(va[r], gx);
        inB[f] = cmul(vb[r], gx);
    }
}

// ---- column pass (dual): FFT(col) -> * gcol -> unnorm IFFT(col), 8 cols/block ----
// Staging uses the P2 mapping; BUFSZ=574 -> cc bank-spacing 28, conflict-free.
// (256,3): regs now 93 natural -> cap 83 costs ~10 regs (rematerializable),
// buying 24 warps/SM instead of 16. smem 3x36.7KB = 110KB < 228KB carveout.
__global__ void __launch_bounds__(256, 3)
k_col(int b0) {
    extern __shared__ float2 sm[];
    const int tid = threadIdx.x;
    const int g = tid >> 6, j = tid & 63;
    const int b = b0 + blockIdx.x;
    const int c0 = blockIdx.y * 8;
    float2* base = g_field + (size_t)b * RES * RES + c0;
    // cooperative transposed load: 8 consecutive threads read 8 consecutive cols (64B)
#pragma unroll
    for (int i = 0; i < 16; i++) {
        int rowi = i * 32 + (tid >> 3);
        int cc = tid & 7;
        sm[(size_t)cc * BUFSZ + P2(rowi)] = base[(size_t)rowi * RES + cc];
    }
    __syncthreads();
    float2* A = sm + (size_t)(2 * g) * BUFSZ;
    float2* B = A + BUFSZ;
    float2 va[8], vb[8];
#pragma unroll
    for (int r = 0; r < 8; r++) { va[r] = A[j + 72 * r]; vb[r] = B[j + 72 * r]; }  // P2(j+64r)
    fft512_reg2<true>(va, vb, j, A, B, 1 + g);    // WAR vs other threads' staged loads
#pragma unroll
    for (int r = 0; r < 8; r++) {
        int f = j + r * 64;
        float2 gc = g_gcol[f];
        va[r] = cconj(cmul(va[r], gc));
        vb[r] = cconj(cmul(vb[r], gc));
    }
    fft512_reg2<true>(va, vb, j, A, B, 1 + g);
    // each thread rewrites exactly the P2 slots it read in the last stage — no hazard
#pragma unroll
    for (int r = 0; r < 8; r++) {
        A[j + 72 * r] = cconj(va[r]);
        B[j + 72 * r] = cconj(vb[r]);
    }
    __syncthreads();
#pragma unroll
    for (int i = 0; i < 16; i++) {
        int rowi = i * 32 + (tid >> 3);
        int cc = tid & 7;
        base[(size_t)rowi * RES + cc] = sm[(size_t)cc * BUFSZ + P2(rowi)];
    }
}

// ---- final row pass: unnorm IFFT(row) -> intensity -> per-row dot with fc_w ----
__global__ void __launch_bounds__(128, 4)
k_row_final(const float* __restrict__ fc_w, int row0) {
    extern __shared__ float2 sm[];
    __shared__ float smred[2][2][NC];
    const int g = threadIdx.x >> 6, j = threadIdx.x & 63;
    const int row = row0 + blockIdx.x * 2 + g;
    const int y = row & 511;
    float2* A = sm + (size_t)g * BUFSZ;
    float2* inrow = g_field + (size_t)row * RES;
    float2 v[8];
#pragma unroll
    for (int r = 0; r < 8; r++) v[r] = cconj(inrow[j + r * 64]);
    fft512_reg<false>(v, j, A, 1 + g);   // |conj(.)|^2 == |.|^2, skip final conj
    float acc[NC];
#pragma unroll
    for (int c = 0; c < NC; c++) acc[c] = 0.0f;
#pragma unroll
    for (int r = 0; r < 8; r++) {
        int i = j + r * 64;
        float2 t = v[r];
        float I = t.x * t.x + t.y * t.y;
        size_t col = (size_t)y * RES + i;
#pragma unroll
        for (int c = 0; c < NC; c++) acc[c] += I * fc_w[(size_t)c * (RES * RES) + col];
    }
#pragma unroll
    for (int c = 0; c < NC; c++) {
#pragma unroll
        for (int off = 16; off > 0; off >>= 1)
            acc[c] += __shfl_down_sync(0xffffffffu, acc[c], off);
    }
    const int lane = j & 31;
    const int half = j >> 5;
    if (lane == 0) {
#pragma unroll
        for (int c = 0; c < NC; c++) smred[g][half][c] = acc[c];
    }
    __syncthreads();
    if (j < NC) g_partial[(size_t)row * NC + j] = smred[g][0][j] + smred[g][1][j];
}

// ---- final reduce: out[b][c] = fc_b[c] + sum_y partial[b*512+y][c] ----
__global__ void k_fc_reduce(const float* __restrict__ fc_b, float* __restrict__ out) {
    const int b = blockIdx.x;
    const int w = threadIdx.x >> 5;
    const int l = threadIdx.x & 31;
    if (w >= NC) return;
    float s = 0.0f;
    for (int y = l; y < RES; y += 32)
        s += g_partial[((size_t)(b << 9) + y) * NC + w];
#pragma unroll
    for (int off = 16; off > 0; off >>= 1)
        s += __shfl_down_sync(0xffffffffu, s, off);
    if (l == 0) out[b * NC + w] = s + fc_b[w];
}

extern "C" void kernel_launch(void* const* d_in, const int* in_sizes, int n_in,
                              void* d_out, int out_size) {
    (void)in_sizes; (void)n_in; (void)out_size;
    const float* x      = (const float*)d_in[0];
    const float* phases = (const float*)d_in[1];
    const float* fc_w   = (const float*)d_in[2];
    const float* fc_b   = (const float*)d_in[3];
    float* out = (float*)d_out;

    const size_t SMEM_ROW  = (size_t)4 * BUFSZ * sizeof(float2);  // 18368 B
    const size_t SMEM_COL  = (size_t)8 * BUFSZ * sizeof(float2);  // 36736 B
    const size_t SMEM_FIN  = (size_t)2 * BUFSZ * sizeof(float2);  //  9184 B
    const int ROW_BLOCKS = CH * RES / 4;                          // 4096 per chunk
    const int FIN_BLOCKS = CH * RES / 2;                          // 8192 per chunk
    const int N_CHUNKS = BATCH / CH;                              // 4

    k_init<<<1, RES>>>();
    k_phexp<<<3 * RES * RES / 1024, 1024>>>(phases);
    // Whole 7-pass pipeline per 32-image chunk: working set stays in L2.
    for (int c = 0; c < N_CHUNKS; c++) {
        const int b0 = c * CH;
        const int row0 = b0 * RES;
        k_row_first<<<ROW_BLOCKS, 128, SMEM_ROW>>>(x, row0);
        for (int layer = 0; layer < 3; layer++) {
            k_col<<<dim3(CH, RES / 8), 256, SMEM_COL>>>(b0);
            if (layer < 2)
                k_row_mid<<<ROW_BLOCKS, 128, SMEM_ROW>>>(layer + 1, row0);
        }
        k_row_final<<<FIN_BLOCKS, 128, SMEM_FIN>>>(fc_w, row0);
    }
    k_fc_reduce<<<BATCH, 320>>>(fc_b, out);
}